// round 14
// baseline (speedup 1.0000x reference)
#include <cuda_runtime.h>
#include <cuda_fp16.h>
#include <cstdint>

// ---------------- problem constants ----------------
#define B_    4
#define C_    64
#define NPIX  1024            // 32*32
#define NB    (B_ * C_ * NPIX)
#define NH    (NB / 2)        // half2 words per split-partial plane set
#define S_    16              // K-split factor
#define CCHUNK 4              // channels per split
#define ASTRIDE 40            // fp16 plane row stride (half2-splat words)
#define HPR   34              // padded rows (0..33)
#define HPLANE (HPR * ASTRIDE)  // words per (b,c) plane
#define KW_   36              // k-steps per split (CCHUNK*9)
#define NQ    (B_ * C_ * 256) // interior quads
#define PADH  336             // pad elements per plane
#define NPADH (PADH * B_ * C_)
#define WPAIR (2 * S_ * KW_ * 32)  // packed half2 weight pairs
#define WSUM  (2 * S_ * 64)        // per-(stage,split,oc) weight sums

// ---------------- scratch (device globals) ----------------
__device__ __align__(16) unsigned int g_ah1[B_ * C_ * HPLANE]; // splat-half2 relu(bn1(x))
__device__ __align__(16) unsigned int g_ah2[B_ * C_ * HPLANE]; // splat-half2 relu(bn2(.))
__device__ __align__(16) unsigned int g_ph1[S_ * NH];  // adder1 partials, half2-packed px pairs
__device__ __align__(16) unsigned int g_ph2[S_ * NH];  // adder2 partials
__device__ float g_out2[NB];                     // adder2 full output
__device__ float g_s[B_ * C_];                   // channel means
__device__ __align__(16) unsigned int g_wh[WPAIR]; // half2 weight pairs
__device__ float g_ws[WSUM];                     // sumW (from fp16-rounded w)

__device__ __forceinline__ unsigned int splat_h(float v) {
    __half2 h2 = __half2half2(__float2half_rn(v));
    return *(unsigned int*)&h2;
}
__device__ __forceinline__ float hlowf(unsigned int u) {
    __half2 h = *(__half2*)&u;
    return __low2float(h);
}
__device__ __forceinline__ float2 h2f2(unsigned int u) {
    return __half22float2(*(__half2*)&u);
}

__device__ __forceinline__ void pad_coord_h(int p, int& r, int& q) {
    if (p < 40)      { r = 0;  q = p; }
    else if (p < 80) { r = 33; q = p - 40; }
    else {
        int t = p - 80;
        r = 1 + (t >> 3);
        int qi = t & 7;
        q = qi ? 32 + qi : 0;                // cols 0,33..39
    }
}

// ------- fused prolog: bn1+relu (fp16 splat), pads(ah1,ah2), weights -----
__global__ void k_pre(const float* __restrict__ xin,
                      const float* __restrict__ gam,
                      const float* __restrict__ bet,
                      const float* __restrict__ mu,
                      const float* __restrict__ var,
                      const float* __restrict__ w1,
                      const float* __restrict__ w2) {
    int idx = blockIdx.x * blockDim.x + threadIdx.x;

    if (idx < NQ) {                          // bn1 + relu interior
        int bc   = idx >> 8;
        int quad = idx & 255;
        int r    = quad >> 3;
        int qx   = (quad & 7) * 4;
        float4 s = *(const float4*)&xin[bc * NPIX + r * 32 + qx];
        int c = bc & (C_ - 1);
        float inv  = gam[c] * rsqrtf(var[c] + 1e-5f);
        float bias = bet[c] - mu[c] * inv;
        unsigned int* ob = g_ah1 + bc * HPLANE + (r + 1) * ASTRIDE + qx + 1;
        ob[0] = splat_h(fmaxf(s.x * inv + bias, 0.f));
        ob[1] = splat_h(fmaxf(s.y * inv + bias, 0.f));
        ob[2] = splat_h(fmaxf(s.z * inv + bias, 0.f));
        ob[3] = splat_h(fmaxf(s.w * inv + bias, 0.f));
    } else if (idx < NQ + 2 * NPADH) {       // zero pads of g_ah1 and g_ah2
        int j = idx - NQ;
        unsigned int* dst = (j < NPADH) ? g_ah1 : g_ah2;
        if (j >= NPADH) j -= NPADH;
        int bc = j / PADH;
        int p  = j - bc * PADH;
        int r, q;
        pad_coord_h(p, r, q);
        dst[bc * HPLANE + r * ASTRIDE + q] = 0u;
    } else if (idx < NQ + 2 * NPADH + WPAIR) { // half2 weight pairs
        int i  = idx - NQ - 2 * NPADH;
        int j  = i & 31;                      // oc pair index
        int t  = i >> 5;
        int k  = t % KW_;
        int sp = (t / KW_) % S_;
        int st = t / (KW_ * S_);
        int cc = k / 9;
        int t9 = k - cc * 9;
        const float* w = st ? w2 : w1;
        float f0 = w[((2 * j)     * C_ + sp * CCHUNK + cc) * 9 + t9];
        float f1 = w[((2 * j + 1) * C_ + sp * CCHUNK + cc) * 9 + t9];
        __half2 h;
        h.x = __float2half_rn(f0);
        h.y = __float2half_rn(f1);
        g_wh[i] = *(unsigned int*)&h;
    } else if (idx < NQ + 2 * NPADH + WPAIR + WSUM) {  // sumW from fp16 w
        int i  = idx - NQ - 2 * NPADH - WPAIR;
        int o  = i & 63;
        int t  = i >> 6;                      // t = st*S_ + sp
        int sp = t % S_;
        int st = t / S_;
        const float* w = st ? w2 : w1;
        float s = 0.f;
#pragma unroll
        for (int cc = 0; cc < CCHUNK; cc++)
#pragma unroll
            for (int t9 = 0; t9 < 9; t9++)
                s += __half2float(__float2half_rn(
                        w[(o * C_ + sp * CCHUNK + cc) * 9 + t9]));
        g_ws[i] = s;
    }
}

// ---------------- stage-1 reduce + bn2 + relu (4-way split-parallel) -----
__global__ void k_red1(const float* __restrict__ gam,
                       const float* __restrict__ bet,
                       const float* __restrict__ mu,
                       const float* __restrict__ var) {
    __shared__ float4 sh[256];
    int tid = threadIdx.x;
    int ql  = tid & 63;
    int spg = tid >> 6;                      // 0..3
    int q   = blockIdx.x * 64 + ql;

    int bc   = q >> 8;
    int quad = q & 255;
    int r    = quad >> 3;
    int qx   = (quad & 7) * 4;
    int ph0  = (bc * NPIX + r * 32 + qx) >> 1;   // half2 index of quad

    float4 s = make_float4(0.f, 0.f, 0.f, 0.f);
#pragma unroll
    for (int k = 0; k < 4; k++) {
        uint2 u = *(const uint2*)&g_ph1[(spg * 4 + k) * NH + ph0];
        float2 f0 = h2f2(u.x), f1 = h2f2(u.y);
        s.x += f0.x; s.y += f0.y; s.z += f1.x; s.w += f1.y;
    }
    sh[spg * 64 + ql] = s;
    __syncthreads();
    if (spg == 0) {
        float4 a = sh[ql], b = sh[64 + ql], c4 = sh[128 + ql], d = sh[192 + ql];
        float4 t;
        t.x = a.x + b.x + c4.x + d.x;
        t.y = a.y + b.y + c4.y + d.y;
        t.z = a.z + b.z + c4.z + d.z;
        t.w = a.w + b.w + c4.w + d.w;
        int c = bc & (C_ - 1);
        float inv  = gam[c] * rsqrtf(var[c] + 1e-5f);
        float bias = bet[c] - mu[c] * inv;
        unsigned int* ob = g_ah2 + bc * HPLANE + (r + 1) * ASTRIDE + qx + 1;
        ob[0] = splat_h(fmaxf(t.x * inv + bias, 0.f));
        ob[1] = splat_h(fmaxf(t.y * inv + bias, 0.f));
        ob[2] = splat_h(fmaxf(t.z * inv + bias, 0.f));
        ob[3] = splat_h(fmaxf(t.w * inv + bias, 0.f));
    }
}

// ---------------- AdderNet conv: packed fp16 min-identity ----------------
// sum|a-w| = sumA + sumW - 2*sum min(a,w), in the fp16-rounded domain
// grid: (128 tiles, 16 splits) = 2048 blocks; block 128 thr
// thread = 4 cols (x0=4*pcol) x 4 oc (2 half2 pairs)
__global__ __launch_bounds__(128, 7) void k_adder(int stage) {
    __shared__ __align__(16) unsigned int AsH[CCHUNK * 3 * ASTRIDE]; // splat half2
    __shared__ __align__(16) unsigned int BsP[KW_ * 32];             // w pairs
    __shared__ float Rs[CCHUNK * 3 * 32];
    __shared__ float sAs[32];

    const unsigned int* aplane = stage ? g_ah2 : g_ah1;
    unsigned int*       part   = stage ? g_ph2 : g_ph1;

    int tid = threadIdx.x;
    int bx  = blockIdx.x;            // 0..127
    int sp  = blockIdx.y;            // 0..15
    int b   = bx >> 5;
    int y   = bx & 31;               // output row
    int c0  = sp * CCHUNK;

    int og   = tid >> 3;             // 0..15 -> oc og*4..og*4+3
    int pcol = tid & 7;
    int x0   = pcol * 4;

    // stage A: pure uint4 copy of 4ch x 3 rows x 40 words from fp16 planes
    {
        const unsigned int* ap = aplane + (b * C_ + c0) * HPLANE + y * ASTRIDE;
        uint4* dst = (uint4*)AsH;
        for (int i = tid; i < CCHUNK * 30; i += 128) {   // 120 uint4
            int cc  = i / 30;
            int rem = i - cc * 30;
            int r   = rem / 10;
            int w4  = rem - r * 10;
            dst[i] = *(const uint4*)(ap + cc * HPLANE + r * ASTRIDE + w4 * 4);
        }
    }
    // stage B: uint4 copy of weight pairs
    {
        const uint4* src = (const uint4*)(g_wh + (stage * S_ + sp) * KW_ * 32);
        uint4* dst = (uint4*)BsP;
        for (int i = tid; i < KW_ * 8; i += 128)   // 1152/4 = 288
            dst[i] = src[i];
    }
    __syncthreads();

    // window sums (fp16-domain values, fp32 accumulate)
    for (int i = tid; i < CCHUNK * 3 * 32; i += 128) {
        int cc  = i / 96;
        int rem = i - cc * 96;
        int r   = rem >> 5;
        int x   = rem & 31;
        const unsigned int* p = &AsH[cc * (3 * ASTRIDE) + r * ASTRIDE + x];
        Rs[i] = hlowf(p[0]) + hlowf(p[1]) + hlowf(p[2]);
    }
    __syncthreads();
    if (tid < 32) {
        float s = 0.f;
#pragma unroll
        for (int cc = 0; cc < CCHUNK; cc++)
#pragma unroll
            for (int r = 0; r < 3; r++)
                s += Rs[cc * 96 + r * 32 + tid];
        sAs[tid] = s;
    }
    __syncthreads();

    unsigned int acc[4][2];
#pragma unroll
    for (int c = 0; c < 4; c++) { acc[c][0] = 0u; acc[c][1] = 0u; }
    float facc[4][4];
#pragma unroll
    for (int c = 0; c < 4; c++)
#pragma unroll
        for (int j = 0; j < 4; j++) facc[c][j] = 0.f;

#pragma unroll
    for (int cc = 0; cc < CCHUNK; ++cc) {
        const unsigned int* base = &AsH[cc * (3 * ASTRIDE)];
#pragma unroll
        for (int kh = 0; kh < 3; ++kh) {
            uint4 q4 = *(const uint4*)(base + kh * ASTRIDE + x0);
            uint2 q2 = *(const uint2*)(base + kh * ASTRIDE + x0 + 4);
            unsigned int rw[6] = {q4.x, q4.y, q4.z, q4.w, q2.x, q2.y};
#pragma unroll
            for (int kw = 0; kw < 3; ++kw) {
                uint2 bp = *(const uint2*)&BsP[(cc * 9 + kh * 3 + kw) * 32 + og * 2];
                __half2 b0 = *(__half2*)&bp.x;
                __half2 b1 = *(__half2*)&bp.y;
#pragma unroll
                for (int c = 0; c < 4; c++) {
                    __half2 a  = *(__half2*)&rw[c + kw];
                    __half2 t0 = __hadd2(*(__half2*)&acc[c][0], __hmin2(a, b0));
                    __half2 t1 = __hadd2(*(__half2*)&acc[c][1], __hmin2(a, b1));
                    acc[c][0] = *(unsigned int*)&t0;
                    acc[c][1] = *(unsigned int*)&t1;
                }
            }
        }
        if (cc & 1) {   // fold every 2 cc (18 fp16 terms max per chunk)
#pragma unroll
            for (int c = 0; c < 4; c++) {
                __half2 a0 = *(__half2*)&acc[c][0];
                __half2 a1 = *(__half2*)&acc[c][1];
                facc[c][0] += __low2float(a0);
                facc[c][1] += __high2float(a0);
                facc[c][2] += __low2float(a1);
                facc[c][3] += __high2float(a1);
                acc[c][0] = 0u; acc[c][1] = 0u;
            }
        }
    }

    // epilogue: partial = 2*summin - sumA - sumW ; store as half2 px pairs
    float sw[4];
#pragma unroll
    for (int j = 0; j < 4; j++)
        sw[j] = g_ws[(stage * S_ + sp) * 64 + og * 4 + j];
    float sa[4];
#pragma unroll
    for (int c = 0; c < 4; c++) sa[c] = sAs[x0 + c];

#pragma unroll
    for (int j = 0; j < 4; j++) {
        float vx = fmaf(2.f, facc[0][j], -sa[0]) - sw[j];
        float vy = fmaf(2.f, facc[1][j], -sa[1]) - sw[j];
        float vz = fmaf(2.f, facc[2][j], -sa[2]) - sw[j];
        float vw = fmaf(2.f, facc[3][j], -sa[3]) - sw[j];
        __half2 h0 = __floats2half2_rn(vx, vy);
        __half2 h1 = __floats2half2_rn(vz, vw);
        uint2 u;
        u.x = *(unsigned int*)&h0;
        u.y = *(unsigned int*)&h1;
        unsigned int* pb = part + ((sp * B_ + b) * C_ + og * 4 + j) * (NPIX / 2)
                         + y * 16 + pcol * 2;
        *(uint2*)pb = u;
    }
}

// ---------------- combine adder2 partials + channel means ----------------
// 256 blocks x 512 thr; 2 threads per quad, each sums 8 of 16 partials
__global__ void k_comb_se() {
    __shared__ float4 sh4[512];
    __shared__ float ws[8];
    int bc  = blockIdx.x;
    int tid = threadIdx.x;  // 0..511
    int ql  = tid & 255;
    int spg = tid >> 8;
    int pix0 = bc * NPIX + ql * 4;
    int ph0  = pix0 >> 1;

    float4 v = make_float4(0.f, 0.f, 0.f, 0.f);
#pragma unroll
    for (int k = 0; k < 8; k++) {
        uint2 u = *(const uint2*)&g_ph2[(spg * 8 + k) * NH + ph0];
        float2 f0 = h2f2(u.x), f1 = h2f2(u.y);
        v.x += f0.x; v.y += f0.y; v.z += f1.x; v.w += f1.y;
    }
    sh4[spg * 256 + ql] = v;
    __syncthreads();
    if (spg == 0) {
        float4 a = sh4[ql], b = sh4[256 + ql];
        float4 t;
        t.x = a.x + b.x; t.y = a.y + b.y; t.z = a.z + b.z; t.w = a.w + b.w;
        *(float4*)&g_out2[pix0] = t;
        float lsum = t.x + t.y + t.z + t.w;
#pragma unroll
        for (int off = 16; off; off >>= 1)
            lsum += __shfl_xor_sync(0xffffffffu, lsum, off);
        if ((tid & 31) == 0) ws[tid >> 5] = lsum;
    }
    __syncthreads();
    if (tid == 0) {
        float t = 0.f;
#pragma unroll
        for (int i = 0; i < 8; i++) t += ws[i];
        g_s[bc] = t * (1.f / 1024.f);
    }
}

// ---------------- final: SE gate (per-block) + out = out2*g + x ----------
__global__ void k_final(const float* __restrict__ x,
                        const float* __restrict__ f1w, const float* __restrict__ f1b,
                        const float* __restrict__ f2w, const float* __restrict__ f2b,
                        float* __restrict__ out) {
    int bc  = blockIdx.x;
    int b   = bc >> 6;
    int c   = bc & 63;
    int tid = threadIdx.x;

    __shared__ float sh[64];
    __shared__ float gg;
    if (tid < 64) sh[tid] = g_s[b * 64 + tid];
    __syncthreads();
    if (tid == 0) {
        float h[4];
#pragma unroll
        for (int j = 0; j < 4; j++) {
            float a = f1b[j];
            for (int c2 = 0; c2 < 64; c2++) a += sh[c2] * f1w[j * 64 + c2];
            h[j] = fmaxf(a, 0.f);
        }
        float z = f2b[c];
#pragma unroll
        for (int j = 0; j < 4; j++) z += h[j] * f2w[c * 4 + j];
        gg = 1.f / (1.f + expf(-z));
    }
    __syncthreads();
    float g = gg;
    int pix0 = bc * NPIX + tid * 4;
    float4 o2 = *(const float4*)&g_out2[pix0];
    float4 xs = *(const float4*)&x[pix0];
    float4 r;
    r.x = o2.x * g + xs.x; r.y = o2.y * g + xs.y;
    r.z = o2.z * g + xs.z; r.w = o2.w * g + xs.w;
    *(float4*)&out[pix0] = r;
}

extern "C" void kernel_launch(void* const* d_in, const int* in_sizes, int n_in,
                              void* d_out, int out_size) {
    const float* x     = (const float*)d_in[0];
    const float* bn1_g = (const float*)d_in[1];
    const float* bn1_b = (const float*)d_in[2];
    const float* bn1_m = (const float*)d_in[3];
    const float* bn1_v = (const float*)d_in[4];
    const float* w1    = (const float*)d_in[5];
    const float* bn2_g = (const float*)d_in[6];
    const float* bn2_b = (const float*)d_in[7];
    const float* bn2_m = (const float*)d_in[8];
    const float* bn2_v = (const float*)d_in[9];
    const float* w2    = (const float*)d_in[10];
    const float* fc1_w = (const float*)d_in[11];
    const float* fc1_b = (const float*)d_in[12];
    const float* fc2_w = (const float*)d_in[13];
    const float* fc2_b = (const float*)d_in[14];
    float* out = (float*)d_out;

    const int pre_tot = NQ + 2 * NPADH + WPAIR + WSUM;
    dim3 ag(128, S_);

    k_pre<<<(pre_tot + 255) / 256, 256>>>(x, bn1_g, bn1_b, bn1_m, bn1_v, w1, w2);
    k_adder<<<ag, 128>>>(0);
    k_red1<<<1024, 256>>>(bn2_g, bn2_b, bn2_m, bn2_v);
    k_adder<<<ag, 128>>>(1);
    k_comb_se<<<256, 512>>>();
    k_final<<<256, 256>>>(x, fc1_w, fc1_b, fc2_w, fc2_b, out);
}

// round 15
// speedup vs baseline: 1.0593x; 1.0593x over previous
#include <cuda_runtime.h>
#include <cuda_fp16.h>
#include <cstdint>

// ---------------- problem constants ----------------
#define B_    4
#define C_    64
#define NPIX  1024            // 32*32
#define NB    (B_ * C_ * NPIX)
#define S_    16              // K-split factor
#define CCHUNK 4              // channels per split
#define ASTRIDE 40            // fp16 plane row stride (half2-splat words)
#define HPR   34              // padded rows (0..33)
#define HPLANE (HPR * ASTRIDE)  // words per (b,c) plane
#define KW_   36              // k-steps per split (CCHUNK*9)
#define NQ    (B_ * C_ * 256) // interior quads
#define PADH  336             // pad elements per plane
#define NPADH (PADH * B_ * C_)
#define WPAIR (2 * S_ * KW_ * 32)  // packed half2 weight pairs
#define WSUM  (2 * S_ * 64)        // per-(stage,split,oc) weight sums

// ---------------- scratch (device globals) ----------------
__device__ __align__(16) unsigned int g_ah1[B_ * C_ * HPLANE]; // splat-half2 relu(bn1(x))
__device__ __align__(16) unsigned int g_ah2[B_ * C_ * HPLANE]; // splat-half2 relu(bn2(.))
__device__ float g_p1[S_ * NB];                  // adder1 partials (fp32, TRUE values)
__device__ float g_p2[S_ * NB];                  // adder2 partials
__device__ float g_out2[NB];                     // adder2 full output
__device__ float g_s[B_ * C_];                   // channel means
__device__ __align__(16) unsigned int g_wh[WPAIR]; // half2 weight pairs
__device__ float g_ws[WSUM];                     // sumW (from fp16-rounded w)

__device__ __forceinline__ unsigned int splat_h(float v) {
    __half2 h2 = __half2half2(__float2half_rn(v));
    return *(unsigned int*)&h2;
}
__device__ __forceinline__ float hlowf(unsigned int u) {
    __half2 h = *(__half2*)&u;
    return __low2float(h);
}

__device__ __forceinline__ void pad_coord_h(int p, int& r, int& q) {
    if (p < 40)      { r = 0;  q = p; }
    else if (p < 80) { r = 33; q = p - 40; }
    else {
        int t = p - 80;
        r = 1 + (t >> 3);
        int qi = t & 7;
        q = qi ? 32 + qi : 0;                // cols 0,33..39
    }
}

// ------- fused prolog: bn1+relu (fp16 splat), pads(ah1,ah2), weights -----
__global__ void k_pre(const float* __restrict__ xin,
                      const float* __restrict__ gam,
                      const float* __restrict__ bet,
                      const float* __restrict__ mu,
                      const float* __restrict__ var,
                      const float* __restrict__ w1,
                      const float* __restrict__ w2) {
    int idx = blockIdx.x * blockDim.x + threadIdx.x;

    if (idx < NQ) {                          // bn1 + relu interior
        int bc   = idx >> 8;
        int quad = idx & 255;
        int r    = quad >> 3;
        int qx   = (quad & 7) * 4;
        float4 s = *(const float4*)&xin[bc * NPIX + r * 32 + qx];
        int c = bc & (C_ - 1);
        float inv  = gam[c] * rsqrtf(var[c] + 1e-5f);
        float bias = bet[c] - mu[c] * inv;
        unsigned int* ob = g_ah1 + bc * HPLANE + (r + 1) * ASTRIDE + qx + 1;
        ob[0] = splat_h(fmaxf(s.x * inv + bias, 0.f));
        ob[1] = splat_h(fmaxf(s.y * inv + bias, 0.f));
        ob[2] = splat_h(fmaxf(s.z * inv + bias, 0.f));
        ob[3] = splat_h(fmaxf(s.w * inv + bias, 0.f));
    } else if (idx < NQ + 2 * NPADH) {       // zero pads of g_ah1 and g_ah2
        int j = idx - NQ;
        unsigned int* dst = (j < NPADH) ? g_ah1 : g_ah2;
        if (j >= NPADH) j -= NPADH;
        int bc = j / PADH;
        int p  = j - bc * PADH;
        int r, q;
        pad_coord_h(p, r, q);
        dst[bc * HPLANE + r * ASTRIDE + q] = 0u;
    } else if (idx < NQ + 2 * NPADH + WPAIR) { // half2 weight pairs
        int i  = idx - NQ - 2 * NPADH;
        int j  = i & 31;                      // oc pair index
        int t  = i >> 5;
        int k  = t % KW_;
        int sp = (t / KW_) % S_;
        int st = t / (KW_ * S_);
        int cc = k / 9;
        int t9 = k - cc * 9;
        const float* w = st ? w2 : w1;
        float f0 = w[((2 * j)     * C_ + sp * CCHUNK + cc) * 9 + t9];
        float f1 = w[((2 * j + 1) * C_ + sp * CCHUNK + cc) * 9 + t9];
        __half2 h;
        h.x = __float2half_rn(f0);
        h.y = __float2half_rn(f1);
        g_wh[i] = *(unsigned int*)&h;
    } else if (idx < NQ + 2 * NPADH + WPAIR + WSUM) {  // sumW from fp16 w
        int i  = idx - NQ - 2 * NPADH - WPAIR;
        int o  = i & 63;
        int t  = i >> 6;                      // t = st*S_ + sp
        int sp = t % S_;
        int st = t / S_;
        const float* w = st ? w2 : w1;
        float s = 0.f;
#pragma unroll
        for (int cc = 0; cc < CCHUNK; cc++)
#pragma unroll
            for (int t9 = 0; t9 < 9; t9++)
                s += __half2float(__float2half_rn(
                        w[(o * C_ + sp * CCHUNK + cc) * 9 + t9]));
        g_ws[i] = s;
    }
}

// ---------------- stage-1 reduce + bn2 + relu (4-way split-parallel) -----
__global__ void k_red1(const float* __restrict__ gam,
                       const float* __restrict__ bet,
                       const float* __restrict__ mu,
                       const float* __restrict__ var) {
    __shared__ float4 sh[256];
    int tid = threadIdx.x;
    int ql  = tid & 63;
    int spg = tid >> 6;                      // 0..3
    int q   = blockIdx.x * 64 + ql;

    int bc   = q >> 8;
    int quad = q & 255;
    int r    = quad >> 3;
    int qx   = (quad & 7) * 4;
    int pix0 = bc * NPIX + r * 32 + qx;

    float4 s = make_float4(0.f, 0.f, 0.f, 0.f);
#pragma unroll
    for (int k = 0; k < 4; k++) {
        float4 p = *(const float4*)&g_p1[(spg * 4 + k) * NB + pix0];
        s.x += p.x; s.y += p.y; s.z += p.z; s.w += p.w;
    }
    sh[spg * 64 + ql] = s;
    __syncthreads();
    if (spg == 0) {
        float4 a = sh[ql], b = sh[64 + ql], c4 = sh[128 + ql], d = sh[192 + ql];
        float4 t;
        t.x = a.x + b.x + c4.x + d.x;
        t.y = a.y + b.y + c4.y + d.y;
        t.z = a.z + b.z + c4.z + d.z;
        t.w = a.w + b.w + c4.w + d.w;
        int c = bc & (C_ - 1);
        float inv  = gam[c] * rsqrtf(var[c] + 1e-5f);
        float bias = bet[c] - mu[c] * inv;
        unsigned int* ob = g_ah2 + bc * HPLANE + (r + 1) * ASTRIDE + qx + 1;
        ob[0] = splat_h(fmaxf(t.x * inv + bias, 0.f));
        ob[1] = splat_h(fmaxf(t.y * inv + bias, 0.f));
        ob[2] = splat_h(fmaxf(t.z * inv + bias, 0.f));
        ob[3] = splat_h(fmaxf(t.w * inv + bias, 0.f));
    }
}

// ---------------- AdderNet conv: packed fp16 min-identity, 2-row tile ----
// sum|a-w| = sumA + sumW - 2*sum min(a,w), in the fp16-rounded domain
// grid: (64 tiles, 16 splits) = 1024 blocks; block 128 thr
// tile = 2 output rows x 32 cols of one image, all 64 oc, 4 channels
// thread = 2 rows x 4 cols (x0=4*pcol) x 4 oc (2 half2 pairs)
__global__ __launch_bounds__(128, 6) void k_adder(int stage) {
    __shared__ __align__(16) unsigned int AsH[CCHUNK * 4 * ASTRIDE]; // splat half2
    __shared__ __align__(16) unsigned int BsP[KW_ * 32];             // w pairs
    __shared__ float Rs[CCHUNK * 4 * 32];
    __shared__ float sAs[64];

    const unsigned int* aplane = stage ? g_ah2 : g_ah1;
    float*              part   = stage ? g_p2  : g_p1;

    int tid = threadIdx.x;
    int bx  = blockIdx.x;            // 0..63
    int sp  = blockIdx.y;            // 0..15
    int b   = bx >> 4;
    int y0  = (bx & 15) * 2;         // output rows y0, y0+1
    int c0  = sp * CCHUNK;

    int og   = tid >> 3;             // 0..15 -> oc og*4..og*4+3
    int pcol = tid & 7;
    int x0   = pcol * 4;

    // stage A: pure uint4 copy of 4ch x 4 padded rows x 40 words
    {
        const unsigned int* ap = aplane + (b * C_ + c0) * HPLANE + y0 * ASTRIDE;
        uint4* dst = (uint4*)AsH;
        for (int i = tid; i < CCHUNK * 40; i += 128) {   // 160 uint4
            int cc  = i / 40;
            int rem = i - cc * 40;
            int r   = rem / 10;
            int w4  = rem - r * 10;
            dst[i] = *(const uint4*)(ap + cc * HPLANE + r * ASTRIDE + w4 * 4);
        }
    }
    // stage B: uint4 copy of weight pairs
    {
        const uint4* src = (const uint4*)(g_wh + (stage * S_ + sp) * KW_ * 32);
        uint4* dst = (uint4*)BsP;
        for (int i = tid; i < KW_ * 8; i += 128)   // 288
            dst[i] = src[i];
    }
    __syncthreads();

    // window sums (fp16-domain values, fp32 accumulate): 4 rows
    for (int i = tid; i < CCHUNK * 4 * 32; i += 128) {
        int cc  = i >> 7;
        int rem = i & 127;
        int r   = rem >> 5;
        int x   = rem & 31;
        const unsigned int* p = &AsH[cc * (4 * ASTRIDE) + r * ASTRIDE + x];
        Rs[i] = hlowf(p[0]) + hlowf(p[1]) + hlowf(p[2]);
    }
    __syncthreads();
    if (tid < 64) {
        int pr = tid >> 5, x = tid & 31;
        float s = 0.f;
#pragma unroll
        for (int cc = 0; cc < CCHUNK; cc++)
#pragma unroll
            for (int kh = 0; kh < 3; kh++)
                s += Rs[cc * 128 + (pr + kh) * 32 + x];
        sAs[tid] = s;
    }
    __syncthreads();

    unsigned int acc[2][4][2];   // [row][col][pair]
#pragma unroll
    for (int pr = 0; pr < 2; pr++)
#pragma unroll
        for (int c = 0; c < 4; c++) { acc[pr][c][0] = 0u; acc[pr][c][1] = 0u; }
    float facc[2][4][4];         // [row][col][oc]
#pragma unroll
    for (int pr = 0; pr < 2; pr++)
#pragma unroll
        for (int c = 0; c < 4; c++)
#pragma unroll
            for (int j = 0; j < 4; j++) facc[pr][c][j] = 0.f;

#pragma unroll
    for (int cc = 0; cc < CCHUNK; ++cc) {
        const unsigned int* base = &AsH[cc * (4 * ASTRIDE)];
        unsigned int rw[4][6];   // 4-row register window, shared by both rows
#pragma unroll
        for (int r = 0; r < 4; r++) {
            uint4 q4 = *(const uint4*)(base + r * ASTRIDE + x0);
            uint2 q2 = *(const uint2*)(base + r * ASTRIDE + x0 + 4);
            rw[r][0] = q4.x; rw[r][1] = q4.y; rw[r][2] = q4.z;
            rw[r][3] = q4.w; rw[r][4] = q2.x; rw[r][5] = q2.y;
        }
#pragma unroll
        for (int kh = 0; kh < 3; ++kh) {
#pragma unroll
            for (int kw = 0; kw < 3; ++kw) {
                uint2 bp = *(const uint2*)&BsP[(cc * 9 + kh * 3 + kw) * 32 + og * 2];
                __half2 b0 = *(__half2*)&bp.x;
                __half2 b1 = *(__half2*)&bp.y;
#pragma unroll
                for (int pr = 0; pr < 2; pr++) {
#pragma unroll
                    for (int c = 0; c < 4; c++) {
                        __half2 a  = *(__half2*)&rw[pr + kh][c + kw];
                        __half2 t0 = __hadd2(*(__half2*)&acc[pr][c][0], __hmin2(a, b0));
                        __half2 t1 = __hadd2(*(__half2*)&acc[pr][c][1], __hmin2(a, b1));
                        acc[pr][c][0] = *(unsigned int*)&t0;
                        acc[pr][c][1] = *(unsigned int*)&t1;
                    }
                }
            }
        }
        if (cc & 1) {   // fold every 2 cc (18 fp16 terms max per chunk)
#pragma unroll
            for (int pr = 0; pr < 2; pr++)
#pragma unroll
                for (int c = 0; c < 4; c++) {
                    __half2 a0 = *(__half2*)&acc[pr][c][0];
                    __half2 a1 = *(__half2*)&acc[pr][c][1];
                    facc[pr][c][0] += __low2float(a0);
                    facc[pr][c][1] += __high2float(a0);
                    facc[pr][c][2] += __low2float(a1);
                    facc[pr][c][3] += __high2float(a1);
                    acc[pr][c][0] = 0u; acc[pr][c][1] = 0u;
                }
        }
    }

    // epilogue: partial = 2*summin - sumA - sumW ; float4 stores
    float sw[4];
#pragma unroll
    for (int j = 0; j < 4; j++)
        sw[j] = g_ws[(stage * S_ + sp) * 64 + og * 4 + j];
    float sa[2][4];
#pragma unroll
    for (int pr = 0; pr < 2; pr++)
#pragma unroll
        for (int c = 0; c < 4; c++) sa[pr][c] = sAs[pr * 32 + x0 + c];

#pragma unroll
    for (int j = 0; j < 4; j++) {
#pragma unroll
        for (int pr = 0; pr < 2; pr++) {
            float4 v;
            v.x = fmaf(2.f, facc[pr][0][j], -sa[pr][0]) - sw[j];
            v.y = fmaf(2.f, facc[pr][1][j], -sa[pr][1]) - sw[j];
            v.z = fmaf(2.f, facc[pr][2][j], -sa[pr][2]) - sw[j];
            v.w = fmaf(2.f, facc[pr][3][j], -sa[pr][3]) - sw[j];
            float* pb = part + ((sp * B_ + b) * C_ + og * 4 + j) * NPIX
                      + (y0 + pr) * 32 + x0;
            *(float4*)pb = v;
        }
    }
}

// ---------------- combine adder2 partials + channel means ----------------
// 256 blocks x 512 thr; 2 threads per quad, each sums 8 of 16 partials
__global__ void k_comb_se() {
    __shared__ float4 sh4[512];
    __shared__ float ws[8];
    int bc  = blockIdx.x;
    int tid = threadIdx.x;  // 0..511
    int ql  = tid & 255;
    int spg = tid >> 8;
    int pix0 = bc * NPIX + ql * 4;

    float4 v = make_float4(0.f, 0.f, 0.f, 0.f);
#pragma unroll
    for (int k = 0; k < 8; k++) {
        float4 p = *(const float4*)&g_p2[(spg * 8 + k) * NB + pix0];
        v.x += p.x; v.y += p.y; v.z += p.z; v.w += p.w;
    }
    sh4[spg * 256 + ql] = v;
    __syncthreads();
    if (spg == 0) {
        float4 a = sh4[ql], b = sh4[256 + ql];
        float4 t;
        t.x = a.x + b.x; t.y = a.y + b.y; t.z = a.z + b.z; t.w = a.w + b.w;
        *(float4*)&g_out2[pix0] = t;
        float lsum = t.x + t.y + t.z + t.w;
#pragma unroll
        for (int off = 16; off; off >>= 1)
            lsum += __shfl_xor_sync(0xffffffffu, lsum, off);
        if ((tid & 31) == 0) ws[tid >> 5] = lsum;
    }
    __syncthreads();
    if (tid == 0) {
        float t = 0.f;
#pragma unroll
        for (int i = 0; i < 8; i++) t += ws[i];
        g_s[bc] = t * (1.f / 1024.f);
    }
}

// ---------------- final: SE gate (per-block) + out = out2*g + x ----------
__global__ void k_final(const float* __restrict__ x,
                        const float* __restrict__ f1w, const float* __restrict__ f1b,
                        const float* __restrict__ f2w, const float* __restrict__ f2b,
                        float* __restrict__ out) {
    int bc  = blockIdx.x;
    int b   = bc >> 6;
    int c   = bc & 63;
    int tid = threadIdx.x;

    __shared__ float sh[64];
    __shared__ float gg;
    if (tid < 64) sh[tid] = g_s[b * 64 + tid];
    __syncthreads();
    if (tid == 0) {
        float h[4];
#pragma unroll
        for (int j = 0; j < 4; j++) {
            float a = f1b[j];
            for (int c2 = 0; c2 < 64; c2++) a += sh[c2] * f1w[j * 64 + c2];
            h[j] = fmaxf(a, 0.f);
        }
        float z = f2b[c];
#pragma unroll
        for (int j = 0; j < 4; j++) z += h[j] * f2w[c * 4 + j];
        gg = 1.f / (1.f + expf(-z));
    }
    __syncthreads();
    float g = gg;
    int pix0 = bc * NPIX + tid * 4;
    float4 o2 = *(const float4*)&g_out2[pix0];
    float4 xs = *(const float4*)&x[pix0];
    float4 r;
    r.x = o2.x * g + xs.x; r.y = o2.y * g + xs.y;
    r.z = o2.z * g + xs.z; r.w = o2.w * g + xs.w;
    *(float4*)&out[pix0] = r;
}

extern "C" void kernel_launch(void* const* d_in, const int* in_sizes, int n_in,
                              void* d_out, int out_size) {
    const float* x     = (const float*)d_in[0];
    const float* bn1_g = (const float*)d_in[1];
    const float* bn1_b = (const float*)d_in[2];
    const float* bn1_m = (const float*)d_in[3];
    const float* bn1_v = (const float*)d_in[4];
    const float* w1    = (const float*)d_in[5];
    const float* bn2_g = (const float*)d_in[6];
    const float* bn2_b = (const float*)d_in[7];
    const float* bn2_m = (const float*)d_in[8];
    const float* bn2_v = (const float*)d_in[9];
    const float* w2    = (const float*)d_in[10];
    const float* fc1_w = (const float*)d_in[11];
    const float* fc1_b = (const float*)d_in[12];
    const float* fc2_w = (const float*)d_in[13];
    const float* fc2_b = (const float*)d_in[14];
    float* out = (float*)d_out;

    const int pre_tot = NQ + 2 * NPADH + WPAIR + WSUM;
    dim3 ag(64, S_);

    k_pre<<<(pre_tot + 255) / 256, 256>>>(x, bn1_g, bn1_b, bn1_m, bn1_v, w1, w2);
    k_adder<<<ag, 128>>>(0);
    k_red1<<<1024, 256>>>(bn2_g, bn2_b, bn2_m, bn2_v);
    k_adder<<<ag, 128>>>(1);
    k_comb_se<<<256, 512>>>();
    k_final<<<256, 256>>>(x, fc1_w, fc1_b, fc2_w, fc2_b, out);
}